// round 14
// baseline (speedup 1.0000x reference)
#include <cuda_runtime.h>

typedef unsigned long long ull;
#define FULL 0xffffffffu
#define PI_4 0.78539816339744830962f
#define SGN2 0x8000000080000000ULL

// ---------------- packed f32x2 helpers ----------------
__device__ __forceinline__ ull pk(float a, float b) {
    ull r; asm("mov.b64 %0, {%1,%2};" : "=l"(r) : "f"(a), "f"(b)); return r;
}
__device__ __forceinline__ void upk(ull v, float &a, float &b) {
    asm("mov.b64 {%0,%1}, %2;" : "=f"(a), "=f"(b) : "l"(v));
}
__device__ __forceinline__ ull fma2(ull a, ull b, ull c) {
    ull d; asm("fma.rn.f32x2 %0, %1, %2, %3;" : "=l"(d) : "l"(a), "l"(b), "l"(c)); return d;
}
__device__ __forceinline__ ull mul2(ull a, ull b) {
    ull d; asm("mul.rn.f32x2 %0, %1, %2;" : "=l"(d) : "l"(a), "l"(b)); return d;
}
__device__ __forceinline__ ull swp(ull v) {
    unsigned lo = (unsigned)v, hi = (unsigned)(v >> 32);
    return ((ull)lo << 32) | hi;
}

// f32x2 pair -> bf16x2 word (lo16 = lo half, hi16 = hi half)
__device__ __forceinline__ unsigned cvtbf(ull v) {
    float a, b; upk(v, a, b);
    unsigned r; asm("cvt.rn.bf16x2.f32 %0, %1, %2;" : "=r"(r) : "f"(b), "f"(a));
    return r;
}
// bf16x2 word -> f32x2 pair (SHL + AND on the ALU pipe; no cvt needed)
__device__ __forceinline__ ull expbf(unsigned h) {
    float lo = __uint_as_float(h << 16);
    float hi = __uint_as_float(h & 0xffff0000u);
    return pk(lo, hi);
}

__device__ __forceinline__ float fast_tanh(float x) {
    float e = __expf(2.0f * x);
    return (e - 1.0f) / (e + 1.0f);
}

// ---------------- compile-time GF(2) schedule (Heisenberg CNOT elimination) ---
// Physical amplitude index bits: [9:5]=lane bits 4..0, [4:1]=reg bits q3..q0,
// [0]=packed half h. Wire w starts on bit (9-w).
// CNOT(c,t): phi_t ^= phi_c, m_c ^= m_t. RY on wire w pairs p <-> p^m_w with
// sign parity(phi_w . p).
struct Sched {
    unsigned m[6][10];
    unsigned phi[6][10];
};
__host__ __device__ constexpr Sched make_sched() {
    Sched S{};
    unsigned phi[10] = {}, m[10] = {};
    for (int w = 0; w < 10; w++) { phi[w] = 1u << (9 - w); m[w] = 1u << (9 - w); }
    const int ctl[9] = {0, 2, 4, 6, 8, 1, 3, 5, 7};
    for (int k = 0; k < 6; k++) {
        for (int g = 0; g < 9; g++) {
            int c = ctl[g], t = c + 1;
            phi[t] ^= phi[c];
            m[c]  ^= m[t];
        }
        for (int w = 0; w < 10; w++) { S.m[k][w] = m[w]; S.phi[k][w] = phi[w]; }
    }
    return S;
}
constexpr Sched SCH = make_sched();

__host__ __device__ constexpr ull make_phbits() {
    ull b = 0;
    Sched S = make_sched();
    for (int k = 0; k < 6; k++)
        for (int w = 0; w < 10; w++)
            if (S.phi[k][w] & 1) b |= 1ull << (k * 10 + w);
    return b;
}
constexpr ull PHB = make_phbits();

__host__ __device__ constexpr int topbit(int x) {
    int b = 0; while (x >> (b + 1)) b++; return 1 << b;
}

// ---------------- one RY gate in the relabeled frame ----------------
// U0 = coeff pack for parity e=0 at h=0; e=1 pack = -U0. |coeff| <= ~0.02, so
// the exchanged partner value may be quantized to bf16 (error suppressed by t).
template<int K, int W>
__device__ __forceinline__ void gate(ull (&sp)[16], int lane, ull U0) {
    constexpr unsigned mm = SCH.m[K][W], pp = SCH.phi[K][W];
    constexpr int LM = (mm >> 5) & 31, RM = (mm >> 1) & 15, HM = mm & 1;
    constexpr int PL = (pp >> 5) & 31, PR = (pp >> 1) & 15;
    ull n0 = U0 ^ SGN2;
    ull Ca, Cb;            // coeff for sigma=0 / sigma=1
    if constexpr (PL != 0) {
        bool f = __popc(lane & PL) & 1;
        Ca = f ? n0 : U0;
        Cb = f ? U0 : n0;
    } else { Ca = U0; Cb = n0; }

    if constexpr (LM == 0 && RM == 0) {
        // intra-pair gate: local, fp32
#pragma unroll
        for (int q = 0; q < 16; q++) {
            ull C = (__popc(q & PR) & 1) ? Cb : Ca;
            sp[q] = fma2(C, swp(sp[q]), sp[q]);
        }
    } else if constexpr (LM == 0) {
        // register-local pairs: fp32
        constexpr int hb = topbit(RM);
#pragma unroll
        for (int q = 0; q < 16; q++) {
            if (!(q & hb)) {
                const int qb = q ^ RM;
                ull a0 = sp[q], a1 = sp[qb];
                ull v0 = HM ? swp(a1) : a1;
                ull v1 = HM ? swp(a0) : a0;
                ull C0 = (__popc(q  & PR) & 1) ? Cb : Ca;
                ull C1 = (__popc(qb & PR) & 1) ? Cb : Ca;
                sp[q]  = fma2(C0, v0, a0);
                sp[qb] = fma2(C1, v1, a1);
            }
        }
    } else if constexpr (RM == 0) {
        // pure lane exchange: bf16 over the crossbar (half the MIO bytes)
#pragma unroll
        for (int q = 0; q < 16; q++) {
            unsigned h  = cvtbf(sp[q]);
            unsigned ph = __shfl_xor_sync(FULL, h, LM);
            if (HM) ph = __byte_perm(ph, 0, 0x1032);   // swap bf16 halves
            ull C = (__popc(q & PR) & 1) ? Cb : Ca;
            sp[q] = fma2(C, expbf(ph), sp[q]);
        }
    } else {
        // lane + register exchange: bf16 over the crossbar
        constexpr int hb = topbit(RM);
#pragma unroll
        for (int q = 0; q < 16; q++) {
            if (!(q & hb)) {
                const int qb = q ^ RM;
                unsigned hA = cvtbf(sp[qb]);
                unsigned hB = cvtbf(sp[q]);
                unsigned pA = __shfl_xor_sync(FULL, hA, LM);
                unsigned pB = __shfl_xor_sync(FULL, hB, LM);
                if (HM) { pA = __byte_perm(pA, 0, 0x1032); pB = __byte_perm(pB, 0, 0x1032); }
                ull C0 = (__popc(q  & PR) & 1) ? Cb : Ca;
                ull C1 = (__popc(qb & PR) & 1) ? Cb : Ca;
                sp[q]  = fma2(C0, expbf(pA), sp[q]);
                sp[qb] = fma2(C1, expbf(pB), sp[qb]);
            }
        }
    }
}

template<int K>
__device__ __forceinline__ void layer(ull (&sp)[16], int lane, const ull (&gU)[10]) {
    gate<K, 0>(sp, lane, gU[0]);
    gate<K, 1>(sp, lane, gU[1]);
    gate<K, 2>(sp, lane, gU[2]);
    gate<K, 3>(sp, lane, gU[3]);
    gate<K, 4>(sp, lane, gU[4]);
    gate<K, 5>(sp, lane, gU[5]);
    gate<K, 6>(sp, lane, gU[6]);
    gate<K, 7>(sp, lane, gU[7]);
    gate<K, 8>(sp, lane, gU[8]);
    gate<K, 9>(sp, lane, gU[9]);
}

// measurement term for wire W from the 32-point WHT F and lane parity
template<int W>
__device__ __forceinline__ float zed(const float (&F)[32], int lane) {
    constexpr unsigned pp = SCH.phi[5][W];
    constexpr int PL = (pp >> 5) & 31;
    constexpr int MR = (((pp >> 1) & 15) << 1) | (pp & 1);
    float v = F[MR];
    if constexpr (PL != 0) { if (__popc(lane & PL) & 1) v = -v; }
    return v;
}

// ---------------- kernel ----------------
__global__ __launch_bounds__(128, 5)
void hybrid_head_kernel(const float* __restrict__ X,       // (B,512)
                        const float* __restrict__ Wpre,    // (10,512)
                        const float* __restrict__ bpre,    // (10,)
                        const float* __restrict__ qp,      // (150,)
                        const float* __restrict__ Wpost,   // (2,10)
                        const float* __restrict__ bpost,   // (2,)
                        float* __restrict__ out,           // (B,2)
                        int B)
{
    __shared__ ull g_U[6][10];
    __shared__ float g_cos[60];
    __shared__ float g_Cs;

    const int tid = threadIdx.x;
    if (tid < 60) {
        int k = tid / 10, w = tid % 10;
        float th = 0.5f * qp[(k + 1) * 10 + w];
        float c = cosf(th), t = tanf(th);
        int PH = (int)((PHB >> (k * 10 + w)) & 1ull);
        g_U[k][w] = pk(-t, PH ? t : -t);
        g_cos[tid] = c;
    }
    __syncthreads();
    if (tid == 0) {
        float prod = 1.0f;
#pragma unroll
        for (int i = 0; i < 60; i++) prod *= g_cos[i];
        g_Cs = prod;
    }
    __syncthreads();

    const int lane   = tid & 31;
    const int sample = blockIdx.x * 4 + (tid >> 5);
    if (sample >= B) return;

    // ---------------- pre-GEMM (packed accumulators) ----------------
    const float4* Xr = reinterpret_cast<const float4*>(X + (size_t)sample * 512);
    float4 xv[4];
#pragma unroll
    for (int j = 0; j < 4; j++) xv[j] = Xr[j * 32 + lane];
    ull xp[8];
#pragma unroll
    for (int j = 0; j < 4; j++) {
        xp[2 * j]     = pk(xv[j].x, xv[j].y);
        xp[2 * j + 1] = pk(xv[j].z, xv[j].w);
    }

    float acc[10];
#pragma unroll
    for (int w = 0; w < 10; w++) {
        const float4* Wr = reinterpret_cast<const float4*>(Wpre + w * 512);
        ull a2 = 0ULL;
#pragma unroll
        for (int j = 0; j < 4; j++) {
            float4 wv = Wr[j * 32 + lane];
            a2 = fma2(xp[2 * j],     pk(wv.x, wv.y), a2);
            a2 = fma2(xp[2 * j + 1], pk(wv.z, wv.w), a2);
        }
        float lo, hi; upk(a2, lo, hi);
        acc[w] = lo + hi;
    }
#pragma unroll
    for (int w = 0; w < 10; w++) {
#pragma unroll
        for (int o = 16; o > 0; o >>= 1)
            acc[w] += __shfl_xor_sync(FULL, acc[w], o);
    }

    // lane w (w<10) owns wire w's angle
    float myc, myt;
    {
        float x = acc[0] + bpre[0];
#pragma unroll
        for (int w = 1; w < 10; w++) {
            float xw = acc[w] + bpre[w];
            x = (lane == w) ? xw : x;
        }
        float th = fast_tanh(x) * PI_4;      // theta/2, |th| <= pi/4
        myc = __cosf(th);
        myt = __tanf(th);                    // |t| <= 1
    }

    // product of the 10 per-sample cosines (masked butterfly)
    float pc = (lane < 10) ? myc : 1.0f;
#pragma unroll
    for (int o = 16; o > 0; o >>= 1)
        pc *= __shfl_xor_sync(FULL, pc, o);

    const int l4 = (lane >> 4) & 1, l3 = (lane >> 3) & 1, l2 = (lane >> 2) & 1,
              l1 = (lane >> 1) & 1, l0 = lane & 1;

    // ---------------- direct product-state construction (fp32 throughout) ----
    ull sp[16];
    {
        float t0 = __shfl_sync(FULL, myt, 0);
        float t1 = __shfl_sync(FULL, myt, 1);
        float t2 = __shfl_sync(FULL, myt, 2);
        float t3 = __shfl_sync(FULL, myt, 3);
        float t4 = __shfl_sync(FULL, myt, 4);
        float t5 = __shfl_sync(FULL, myt, 5);
        float t6 = __shfl_sync(FULL, myt, 6);
        float t7 = __shfl_sync(FULL, myt, 7);
        float t8 = __shfl_sync(FULL, myt, 8);
        float t9 = __shfl_sync(FULL, myt, 9);

        float F = (1.0f + (l4 ? t0 : -t0));
        F *= (1.0f + (l3 ? t1 : -t1));
        F *= (1.0f + (l2 ? t2 : -t2));
        F *= (1.0f + (l1 ? t3 : -t3));
        F *= (1.0f + (l0 ? t4 : -t4));
        float FA = F * (pc * g_Cs * 0.03125f);

        ull PP = pk(FA * (1.0f - t9), FA * (1.0f + t9));

        float m5[2] = {1.0f - t5, 1.0f + t5};
        float m6[2] = {1.0f - t6, 1.0f + t6};
        float m7[2] = {1.0f - t7, 1.0f + t7};
        float m8[2] = {1.0f - t8, 1.0f + t8};
        float g4[4], g8[8];
#pragma unroll
        for (int i = 0; i < 4; i++) g4[i] = m5[(i >> 1) & 1] * m6[i & 1];
#pragma unroll
        for (int i = 0; i < 8; i++) g8[i] = g4[i >> 1] * m7[i & 1];
#pragma unroll
        for (int q = 0; q < 16; q++) {
            float g = g8[q >> 1] * m8[q & 1];
            sp[q] = mul2(pk(g, g), PP);
        }
    }

    // ---------------- 6 entangling+RY layers (CNOTs are free relabelings) ----
    layer<0>(sp, lane, g_U[0]);
    layer<1>(sp, lane, g_U[1]);
    layer<2>(sp, lane, g_U[2]);
    layer<3>(sp, lane, g_U[3]);
    layer<4>(sp, lane, g_U[4]);
    layer<5>(sp, lane, g_U[5]);

    // ---------------- measurement: probs -> 32-pt WHT -> z via final phi -----
    float F[32];
#pragma unroll
    for (int q = 0; q < 16; q++) {
        float lo, hi; upk(sp[q], lo, hi);
        F[2 * q]     = lo * lo;
        F[2 * q + 1] = hi * hi;
    }
#pragma unroll
    for (int b = 0; b < 5; b++) {
        const int mk = 1 << b;
#pragma unroll
        for (int r = 0; r < 32; r++) {
            if (!(r & mk)) {
                float a = F[r], c = F[r | mk];
                F[r]      = a + c;
                F[r | mk] = a - c;
            }
        }
    }

    float z[10];
    z[0] = zed<0>(F, lane);
    z[1] = zed<1>(F, lane);
    z[2] = zed<2>(F, lane);
    z[3] = zed<3>(F, lane);
    z[4] = zed<4>(F, lane);
    z[5] = zed<5>(F, lane);
    z[6] = zed<6>(F, lane);
    z[7] = zed<7>(F, lane);
    z[8] = zed<8>(F, lane);
    z[9] = zed<9>(F, lane);

#pragma unroll
    for (int w = 0; w < 10; w++) {
#pragma unroll
        for (int o = 16; o > 0; o >>= 1)
            z[w] += __shfl_xor_sync(FULL, z[w], o);
    }

    // ---------------- post-GEMM ----------------
    if (lane == 0) {
        float o0 = bpost[0], o1 = bpost[1];
#pragma unroll
        for (int w = 0; w < 10; w++) {
            o0 = fmaf(z[w], Wpost[w],      o0);
            o1 = fmaf(z[w], Wpost[10 + w], o1);
        }
        reinterpret_cast<float2*>(out)[sample] = make_float2(o0, o1);
    }
}

extern "C" void kernel_launch(void* const* d_in, const int* in_sizes, int n_in,
                              void* d_out, int out_size)
{
    const float* X     = (const float*)d_in[0];
    const float* Wpre  = (const float*)d_in[1];
    const float* bpre  = (const float*)d_in[2];
    const float* qp    = (const float*)d_in[3];
    const float* Wpost = (const float*)d_in[4];
    const float* bpost = (const float*)d_in[5];
    float* out = (float*)d_out;

    int B = in_sizes[0] / 512;           // 8192
    int blocks = (B + 3) / 4;            // 4 samples (warps) per 128-thread block
    hybrid_head_kernel<<<blocks, 128>>>(X, Wpre, bpre, qp, Wpost, bpost, out, B);
}

// round 15
// speedup vs baseline: 1.1712x; 1.1712x over previous
#include <cuda_runtime.h>

typedef unsigned long long ull;
#define FULL 0xffffffffu
#define PI_4 0.78539816339744830962f
#define SGN2 0x8000000080000000ULL

// ---------------- packed f32x2 helpers ----------------
__device__ __forceinline__ ull pk(float a, float b) {
    ull r; asm("mov.b64 %0, {%1,%2};" : "=l"(r) : "f"(a), "f"(b)); return r;
}
__device__ __forceinline__ void upk(ull v, float &a, float &b) {
    asm("mov.b64 {%0,%1}, %2;" : "=f"(a), "=f"(b) : "l"(v));
}
__device__ __forceinline__ ull fma2(ull a, ull b, ull c) {
    ull d; asm("fma.rn.f32x2 %0, %1, %2, %3;" : "=l"(d) : "l"(a), "l"(b), "l"(c)); return d;
}
__device__ __forceinline__ ull mul2(ull a, ull b) {
    ull d; asm("mul.rn.f32x2 %0, %1, %2;" : "=l"(d) : "l"(a), "l"(b)); return d;
}
__device__ __forceinline__ ull add2(ull a, ull b) {
    ull d; asm("add.rn.f32x2 %0, %1, %2;" : "=l"(d) : "l"(a), "l"(b)); return d;
}
__device__ __forceinline__ ull swp(ull v) {
    unsigned lo = (unsigned)v, hi = (unsigned)(v >> 32);
    return ((ull)lo << 32) | hi;
}

__device__ __forceinline__ float fast_tanh(float x) {
    float e = __expf(2.0f * x);
    return (e - 1.0f) / (e + 1.0f);
}

// ---------------- compile-time GF(2) schedule (Heisenberg CNOT elimination) ---
// Physical amplitude index bits: [9:5]=lane bits 4..0, [4:1]=reg bits q3..q0,
// [0]=packed half h. Wire w starts on bit (9-w).
// CNOT(c,t): phi_t ^= phi_c, m_c ^= m_t. RY on wire w pairs p <-> p^m_w with
// sign parity(phi_w . p).
struct Sched {
    unsigned m[6][10];
    unsigned phi[6][10];
};
__host__ __device__ constexpr Sched make_sched() {
    Sched S{};
    unsigned phi[10] = {}, m[10] = {};
    for (int w = 0; w < 10; w++) { phi[w] = 1u << (9 - w); m[w] = 1u << (9 - w); }
    const int ctl[9] = {0, 2, 4, 6, 8, 1, 3, 5, 7};
    for (int k = 0; k < 6; k++) {
        for (int g = 0; g < 9; g++) {
            int c = ctl[g], t = c + 1;
            phi[t] ^= phi[c];
            m[c]  ^= m[t];
        }
        for (int w = 0; w < 10; w++) { S.m[k][w] = m[w]; S.phi[k][w] = phi[w]; }
    }
    return S;
}
constexpr Sched SCH = make_sched();

__host__ __device__ constexpr ull make_phbits() {
    ull b = 0;
    Sched S = make_sched();
    for (int k = 0; k < 6; k++)
        for (int w = 0; w < 10; w++)
            if (S.phi[k][w] & 1) b |= 1ull << (k * 10 + w);
    return b;
}
constexpr ull PHB = make_phbits();

__host__ __device__ constexpr int topbit(int x) {
    int b = 0; while (x >> (b + 1)) b++; return 1 << b;
}

// ---------------- one RY gate in the relabeled frame (fp32 exchanges) --------
// U0 = coeff pack for parity e=0 at h=0; e=1 pack = -U0.
template<int K, int W>
__device__ __forceinline__ void gate(ull (&sp)[16], int lane, ull U0) {
    constexpr unsigned mm = SCH.m[K][W], pp = SCH.phi[K][W];
    constexpr int LM = (mm >> 5) & 31, RM = (mm >> 1) & 15, HM = mm & 1;
    constexpr int PL = (pp >> 5) & 31, PR = (pp >> 1) & 15;
    ull n0 = U0 ^ SGN2;
    ull Ca, Cb;            // coeff for sigma=0 / sigma=1
    if constexpr (PL != 0) {
        bool f = __popc(lane & PL) & 1;
        Ca = f ? n0 : U0;
        Cb = f ? U0 : n0;
    } else { Ca = U0; Cb = n0; }

    if constexpr (LM == 0 && RM == 0) {
#pragma unroll
        for (int q = 0; q < 16; q++) {
            ull C = (__popc(q & PR) & 1) ? Cb : Ca;
            sp[q] = fma2(C, swp(sp[q]), sp[q]);
        }
    } else if constexpr (LM == 0) {
        constexpr int hb = topbit(RM);
#pragma unroll
        for (int q = 0; q < 16; q++) {
            if (!(q & hb)) {
                const int qb = q ^ RM;
                ull a0 = sp[q], a1 = sp[qb];
                ull v0 = HM ? swp(a1) : a1;
                ull v1 = HM ? swp(a0) : a0;
                ull C0 = (__popc(q  & PR) & 1) ? Cb : Ca;
                ull C1 = (__popc(qb & PR) & 1) ? Cb : Ca;
                sp[q]  = fma2(C0, v0, a0);
                sp[qb] = fma2(C1, v1, a1);
            }
        }
    } else if constexpr (RM == 0) {
#pragma unroll
        for (int q = 0; q < 16; q++) {
            ull v = __shfl_xor_sync(FULL, sp[q], LM);
            if (HM) v = swp(v);
            ull C = (__popc(q & PR) & 1) ? Cb : Ca;
            sp[q] = fma2(C, v, sp[q]);
        }
    } else {
        constexpr int hb = topbit(RM);
#pragma unroll
        for (int q = 0; q < 16; q++) {
            if (!(q & hb)) {
                const int qb = q ^ RM;
                ull vA = __shfl_xor_sync(FULL, sp[qb], LM);
                ull vB = __shfl_xor_sync(FULL, sp[q],  LM);
                if (HM) { vA = swp(vA); vB = swp(vB); }
                ull C0 = (__popc(q  & PR) & 1) ? Cb : Ca;
                ull C1 = (__popc(qb & PR) & 1) ? Cb : Ca;
                sp[q]  = fma2(C0, vA, sp[q]);
                sp[qb] = fma2(C1, vB, sp[qb]);
            }
        }
    }
}

template<int K>
__device__ __forceinline__ void layer(ull (&sp)[16], int lane, const ull (&gU)[10]) {
    gate<K, 0>(sp, lane, gU[0]);
    gate<K, 1>(sp, lane, gU[1]);
    gate<K, 2>(sp, lane, gU[2]);
    gate<K, 3>(sp, lane, gU[3]);
    gate<K, 4>(sp, lane, gU[4]);
    gate<K, 5>(sp, lane, gU[5]);
    gate<K, 6>(sp, lane, gU[6]);
    gate<K, 7>(sp, lane, gU[7]);
    gate<K, 8>(sp, lane, gU[8]);
    gate<K, 9>(sp, lane, gU[9]);
}

// measurement term for wire W from the 32-point WHT F and lane parity
template<int W>
__device__ __forceinline__ float zed(const float (&F)[32], int lane) {
    constexpr unsigned pp = SCH.phi[5][W];
    constexpr int PL = (pp >> 5) & 31;
    constexpr int MR = (((pp >> 1) & 15) << 1) | (pp & 1);
    float v = F[MR];
    if constexpr (PL != 0) { if (__popc(lane & PL) & 1) v = -v; }
    return v;
}

// ---------------- kernel ----------------
__global__ __launch_bounds__(128, 6)
void hybrid_head_kernel(const float* __restrict__ X,       // (B,512)
                        const float* __restrict__ Wpre,    // (10,512)
                        const float* __restrict__ bpre,    // (10,)
                        const float* __restrict__ qp,      // (150,)
                        const float* __restrict__ Wpost,   // (2,10)
                        const float* __restrict__ bpost,   // (2,)
                        float* __restrict__ out,           // (B,2)
                        int B)
{
    __shared__ ull g_U[6][10];
    __shared__ float g_cos[60];
    __shared__ float g_Cs;

    const int tid = threadIdx.x;
    if (tid < 60) {
        int k = tid / 10, w = tid % 10;
        float th = 0.5f * qp[(k + 1) * 10 + w];
        float c = cosf(th), t = tanf(th);
        int PH = (int)((PHB >> (k * 10 + w)) & 1ull);
        g_U[k][w] = pk(-t, PH ? t : -t);
        g_cos[tid] = c;
    }
    __syncthreads();
    if (tid == 0) {
        float prod = 1.0f;
#pragma unroll
        for (int i = 0; i < 60; i++) prod *= g_cos[i];
        g_Cs = prod;
    }
    __syncthreads();

    const int lane   = tid & 31;
    const int sample = blockIdx.x * 4 + (tid >> 5);
    if (sample >= B) return;

    // ---------------- pre-GEMM (packed accumulators) ----------------
    const float4* Xr = reinterpret_cast<const float4*>(X + (size_t)sample * 512);
    float4 xv[4];
#pragma unroll
    for (int j = 0; j < 4; j++) xv[j] = Xr[j * 32 + lane];
    ull xp[8];
#pragma unroll
    for (int j = 0; j < 4; j++) {
        xp[2 * j]     = pk(xv[j].x, xv[j].y);
        xp[2 * j + 1] = pk(xv[j].z, xv[j].w);
    }

    float acc[10];
#pragma unroll
    for (int w = 0; w < 10; w++) {
        const float4* Wr = reinterpret_cast<const float4*>(Wpre + w * 512);
        ull a2 = 0ULL;
#pragma unroll
        for (int j = 0; j < 4; j++) {
            float4 wv = Wr[j * 32 + lane];
            a2 = fma2(xp[2 * j],     pk(wv.x, wv.y), a2);
            a2 = fma2(xp[2 * j + 1], pk(wv.z, wv.w), a2);
        }
        float lo, hi; upk(a2, lo, hi);
        acc[w] = lo + hi;
    }

    // packed warp reduction: 5 ull pairs, 25 shfl.64 + 25 add2
    ull ap[5];
#pragma unroll
    for (int i = 0; i < 5; i++) ap[i] = pk(acc[2 * i], acc[2 * i + 1]);
#pragma unroll
    for (int i = 0; i < 5; i++) {
#pragma unroll
        for (int o = 16; o > 0; o >>= 1)
            ap[i] = add2(ap[i], __shfl_xor_sync(FULL, ap[i], o));
    }

    // lane w (w<10) owns wire w's angle: select its pair + half
    float myc, myt;
    {
        ull mp = ap[0];
        if (lane >= 2) mp = ap[1];
        if (lane >= 4) mp = ap[2];
        if (lane >= 6) mp = ap[3];
        if (lane >= 8) mp = ap[4];
        float lo, hi; upk(mp, lo, hi);
        float x = ((lane & 1) ? hi : lo) + bpre[lane < 10 ? lane : 0];
        float th = fast_tanh(x) * PI_4;      // theta/2, |th| <= pi/4
        myc = __cosf(th);
        myt = __tanf(th);                    // |t| <= 1
    }

    // product of the 10 per-sample cosines (masked butterfly)
    float pc = (lane < 10) ? myc : 1.0f;
#pragma unroll
    for (int o = 16; o > 0; o >>= 1)
        pc *= __shfl_xor_sync(FULL, pc, o);

    const int l4 = (lane >> 4) & 1, l3 = (lane >> 3) & 1, l2 = (lane >> 2) & 1,
              l1 = (lane >> 1) & 1, l0 = lane & 1;

    // ---------------- direct product-state construction ----------------
    // amp(b) = A * prod_w (b_w ? 1+t_w : 1-t_w), A = (1/32)*prod(cos)
    ull sp[16];
    {
        float t0 = __shfl_sync(FULL, myt, 0);
        float t1 = __shfl_sync(FULL, myt, 1);
        float t2 = __shfl_sync(FULL, myt, 2);
        float t3 = __shfl_sync(FULL, myt, 3);
        float t4 = __shfl_sync(FULL, myt, 4);
        float t5 = __shfl_sync(FULL, myt, 5);
        float t6 = __shfl_sync(FULL, myt, 6);
        float t7 = __shfl_sync(FULL, myt, 7);
        float t8 = __shfl_sync(FULL, myt, 8);
        float t9 = __shfl_sync(FULL, myt, 9);

        float F = (1.0f + (l4 ? t0 : -t0));
        F *= (1.0f + (l3 ? t1 : -t1));
        F *= (1.0f + (l2 ? t2 : -t2));
        F *= (1.0f + (l1 ? t3 : -t3));
        F *= (1.0f + (l0 ? t4 : -t4));
        float FA = F * (pc * g_Cs * 0.03125f);

        ull PP = pk(FA * (1.0f - t9), FA * (1.0f + t9));

        float m5[2] = {1.0f - t5, 1.0f + t5};
        float m6[2] = {1.0f - t6, 1.0f + t6};
        float m7[2] = {1.0f - t7, 1.0f + t7};
        float m8[2] = {1.0f - t8, 1.0f + t8};
        float g4[4], g8[8];
#pragma unroll
        for (int i = 0; i < 4; i++) g4[i] = m5[(i >> 1) & 1] * m6[i & 1];
#pragma unroll
        for (int i = 0; i < 8; i++) g8[i] = g4[i >> 1] * m7[i & 1];
#pragma unroll
        for (int q = 0; q < 16; q++) {
            float g = g8[q >> 1] * m8[q & 1];
            sp[q] = mul2(pk(g, g), PP);
        }
    }

    // ---------------- 6 entangling+RY layers (CNOTs are free relabelings) ----
    layer<0>(sp, lane, g_U[0]);
    layer<1>(sp, lane, g_U[1]);
    layer<2>(sp, lane, g_U[2]);
    layer<3>(sp, lane, g_U[3]);
    layer<4>(sp, lane, g_U[4]);
    layer<5>(sp, lane, g_U[5]);

    // ---------------- measurement: probs -> 32-pt WHT -> z via final phi -----
    float F[32];
#pragma unroll
    for (int q = 0; q < 16; q++) {
        float lo, hi; upk(sp[q], lo, hi);
        F[2 * q]     = lo * lo;
        F[2 * q + 1] = hi * hi;
    }
#pragma unroll
    for (int b = 0; b < 5; b++) {
        const int mk = 1 << b;
#pragma unroll
        for (int r = 0; r < 32; r++) {
            if (!(r & mk)) {
                float a = F[r], c = F[r | mk];
                F[r]      = a + c;
                F[r | mk] = a - c;
            }
        }
    }

    // per-lane partial post-GEMM, then ONE packed reduction
    float p0 = 0.0f, p1 = 0.0f;
    {
        float zv;
        zv = zed<0>(F, lane); p0 = fmaf(zv, __ldg(&Wpost[0]), p0); p1 = fmaf(zv, __ldg(&Wpost[10]), p1);
        zv = zed<1>(F, lane); p0 = fmaf(zv, __ldg(&Wpost[1]), p0); p1 = fmaf(zv, __ldg(&Wpost[11]), p1);
        zv = zed<2>(F, lane); p0 = fmaf(zv, __ldg(&Wpost[2]), p0); p1 = fmaf(zv, __ldg(&Wpost[12]), p1);
        zv = zed<3>(F, lane); p0 = fmaf(zv, __ldg(&Wpost[3]), p0); p1 = fmaf(zv, __ldg(&Wpost[13]), p1);
        zv = zed<4>(F, lane); p0 = fmaf(zv, __ldg(&Wpost[4]), p0); p1 = fmaf(zv, __ldg(&Wpost[14]), p1);
        zv = zed<5>(F, lane); p0 = fmaf(zv, __ldg(&Wpost[5]), p0); p1 = fmaf(zv, __ldg(&Wpost[15]), p1);
        zv = zed<6>(F, lane); p0 = fmaf(zv, __ldg(&Wpost[6]), p0); p1 = fmaf(zv, __ldg(&Wpost[16]), p1);
        zv = zed<7>(F, lane); p0 = fmaf(zv, __ldg(&Wpost[7]), p0); p1 = fmaf(zv, __ldg(&Wpost[17]), p1);
        zv = zed<8>(F, lane); p0 = fmaf(zv, __ldg(&Wpost[8]), p0); p1 = fmaf(zv, __ldg(&Wpost[18]), p1);
        zv = zed<9>(F, lane); p0 = fmaf(zv, __ldg(&Wpost[9]), p0); p1 = fmaf(zv, __ldg(&Wpost[19]), p1);
    }
    ull pz = pk(p0, p1);
#pragma unroll
    for (int o = 16; o > 0; o >>= 1)
        pz = add2(pz, __shfl_xor_sync(FULL, pz, o));

    if (lane == 0) {
        float o0, o1; upk(pz, o0, o1);
        reinterpret_cast<float2*>(out)[sample] =
            make_float2(o0 + bpost[0], o1 + bpost[1]);
    }
}

extern "C" void kernel_launch(void* const* d_in, const int* in_sizes, int n_in,
                              void* d_out, int out_size)
{
    const float* X     = (const float*)d_in[0];
    const float* Wpre  = (const float*)d_in[1];
    const float* bpre  = (const float*)d_in[2];
    const float* qp    = (const float*)d_in[3];
    const float* Wpost = (const float*)d_in[4];
    const float* bpost = (const float*)d_in[5];
    float* out = (float*)d_out;

    int B = in_sizes[0] / 512;           // 8192
    int blocks = (B + 3) / 4;            // 4 samples (warps) per 128-thread block
    hybrid_head_kernel<<<blocks, 128>>>(X, Wpre, bpre, qp, Wpost, bpost, out, B);
}